// round 17
// baseline (speedup 1.0000x reference)
#include <cuda_runtime.h>
#include <cuda_bf16.h>
#include <cuda_fp16.h>
#include <math.h>
#include <stdint.h>

#define LQ 1024
#define BB 16
#define FF 512
#define HH 8
#define KK 64
#define TEMPS 30.0f
#define BH 128

// ------------------------- static scratch -------------------------
// X (query/key) as split-bf16 A-fragments: [inp][b][q16 0..63][kc 0..31][lane] uint4
__device__ __align__(16) uint4 g_xA1[(size_t)2 * 16 * 64 * 32 * 32];
__device__ __align__(16) uint4 g_xA2[(size_t)2 * 16 * 64 * 32 * 32];
// W as split-bf16 B-fragments: [n8 0..63][kc 0..31][lane] uint2
__device__ __align__(16) uint2 g_wB1[(size_t)64 * 32 * 32];
__device__ __align__(16) uint2 g_wB2[(size_t)64 * 32 * 32];
// wq as A-fragments: [bh][q16 0..63][k16 0..3][lane] uint4, 2 parts
__device__ __align__(16) uint4 g_wqA1[(size_t)BH * 64 * 4 * 32];
__device__ __align__(16) uint4 g_wqA2[(size_t)BH * 64 * 4 * 32];
// wk as B-fragments: [bh][n8 0..127][k16 0..3][lane] uint2, 2 parts
__device__ __align__(16) uint2 g_wkB1[(size_t)BH * 128 * 4 * 32];
__device__ __align__(16) uint2 g_wkB2[(size_t)BH * 128 * 4 * 32];
// V (hi fp16) B-fragments: [b][f8 0..63][s16 0..63][lane] uint2
__device__ __align__(16) uint32_t g_vt[(size_t)BB * 64 * 64 * 32 * 2];

// ------------------------- helpers -------------------------
__device__ __forceinline__ void split2pack(float x, float y, uint32_t& hi, uint32_t& lo) {
    __nv_bfloat16 hx = __float2bfloat16(x), hy = __float2bfloat16(y);
    __nv_bfloat16 lx = __float2bfloat16(x - __bfloat162float(hx));
    __nv_bfloat16 ly = __float2bfloat16(y - __bfloat162float(hy));
    __nv_bfloat162 H = __halves2bfloat162(hx, hy);
    __nv_bfloat162 L = __halves2bfloat162(lx, ly);
    hi = *(uint32_t*)&H;
    lo = *(uint32_t*)&L;
}
__device__ __forceinline__ void mma_bf16(float c[4], uint32_t a0, uint32_t a1, uint32_t a2,
                                         uint32_t a3, uint32_t b0, uint32_t b1) {
    asm("mma.sync.aligned.m16n8k16.row.col.f32.bf16.bf16.f32 "
        "{%0,%1,%2,%3}, {%4,%5,%6,%7}, {%8,%9}, {%0,%1,%2,%3};"
        : "+f"(c[0]), "+f"(c[1]), "+f"(c[2]), "+f"(c[3])
        : "r"(a0), "r"(a1), "r"(a2), "r"(a3), "r"(b0), "r"(b1));
}
__device__ __forceinline__ void mma_f16(float c[4], uint32_t a0, uint32_t a1, uint32_t a2,
                                        uint32_t a3, uint32_t b0, uint32_t b1) {
    asm("mma.sync.aligned.m16n8k16.row.col.f32.f16.f16.f32 "
        "{%0,%1,%2,%3}, {%4,%5,%6,%7}, {%8,%9}, {%0,%1,%2,%3};"
        : "+f"(c[0]), "+f"(c[1]), "+f"(c[2]), "+f"(c[3])
        : "r"(a0), "r"(a1), "r"(a2), "r"(a3), "r"(b0), "r"(b1));
}
extern __shared__ __align__(1024) char smx[];

// ---------------------------------------------------------------------------
// Kernel 0a: W -> split-bf16 B-fragments. grid(64 n8), 256 thr.
// ---------------------------------------------------------------------------
__global__ __launch_bounds__(256) void wsplit_kernel(const float* __restrict__ W) {
    const int w = threadIdx.x >> 5, lane = threadIdx.x & 31;
    const int g = lane >> 2, tig = lane & 3;
    const int n8 = blockIdx.x;
    const int n = n8 * 8 + g;
#pragma unroll
    for (int u = 0; u < 4; u++) {
        const int kc = w * 4 + u;
        float2 w0 = *(const float2*)(W + (size_t)n * FF + kc * 16 + tig * 2);
        float2 w1 = *(const float2*)(W + (size_t)n * FF + kc * 16 + 8 + tig * 2);
        uint2 u1, u2;
        split2pack(w0.x, w0.y, u1.x, u2.x);
        split2pack(w1.x, w1.y, u1.y, u2.y);
        const size_t idx = ((size_t)n8 * 32 + kc) * 32 + lane;
        g_wB1[idx] = u1;
        g_wB2[idx] = u2;
    }
}

// ---------------------------------------------------------------------------
// Kernel 0b: X (query & key) -> split-bf16 A-fragments.
// ---------------------------------------------------------------------------
__global__ __launch_bounds__(256) void xsplit_kernel(const float* __restrict__ Q,
                                                     const float* __restrict__ Kx) {
    const int w = threadIdx.x >> 5, lane = threadIdx.x & 31;
    const int g = lane >> 2, tig = lane & 3;
    const int q16 = blockIdx.x, b = blockIdx.y, inp = blockIdx.z;
    const float* X = inp ? Kx : Q;
    const int r0 = q16 * 16 + g;
    const float* p0 = X + ((size_t)r0 * BB + b) * FF;
    const float* p1 = X + ((size_t)(r0 + 8) * BB + b) * FF;
#pragma unroll
    for (int u = 0; u < 4; u++) {
        const int kc = w * 4 + u;
        const int k0 = kc * 16 + tig * 2;
        float2 v00 = *(const float2*)(p0 + k0);
        float2 v10 = *(const float2*)(p1 + k0);
        float2 v01 = *(const float2*)(p0 + k0 + 8);
        float2 v11 = *(const float2*)(p1 + k0 + 8);
        uint4 u1, u2;
        split2pack(v00.x, v00.y, u1.x, u2.x);
        split2pack(v10.x, v10.y, u1.y, u2.y);
        split2pack(v01.x, v01.y, u1.z, u2.z);
        split2pack(v11.x, v11.y, u1.w, u2.w);
        const size_t idx = ((((size_t)inp * 16 + b) * 64 + q16) * 32 + kc) * 32 + lane;
        g_xA1[idx] = u1;
        g_xA2[idx] = u2;
    }
}

// ---------------------------------------------------------------------------
// Kernel 1: projection, fragment-native (unchanged from round 16).
// ---------------------------------------------------------------------------
__global__ __launch_bounds__(256) void projmma_kernel(const float* __restrict__ bias) {
    __shared__ float ssq[128][2];
    const int tid = threadIdx.x;
    const int w = tid >> 5, lane = tid & 31;
    const int g = lane >> 2, tig = lane & 3;
    const int qw = w >> 1, nw = w & 1;
    const int bx = blockIdx.x;
    const int qt = bx >> 4, b = bx & 15;
    const int h = blockIdx.y;
    const int isQ = (blockIdx.z == 0);
    const float scale = isQ ? TEMPS : 1.0f;
    const int n0 = h * 64;
    const size_t bh = (size_t)b * HH + h;
    const size_t ib_ = (size_t)blockIdx.z * 16 + b;

    float acc[2][4][4] = {};

    for (int kc = 0; kc < 32; kc++) {
        uint4 A1[2], A2[2];
#pragma unroll
        for (int mi = 0; mi < 2; mi++) {
            const size_t ia = ((ib_ * 64 + qt * 8 + qw * 2 + mi) * 32 + kc) * 32 + lane;
            A1[mi] = g_xA1[ia];
            A2[mi] = g_xA2[ia];
        }
#pragma unroll
        for (int j = 0; j < 2; j++) {
#pragma unroll
            for (int nn = 0; nn < 2; nn++) {
                const int n8 = h * 8 + nw * 4 + j * 2 + nn;
                const size_t ibx = ((size_t)n8 * 32 + kc) * 32 + lane;
                uint2 B1 = g_wB1[ibx];
                uint2 B2 = g_wB2[ibx];
#pragma unroll
                for (int mi = 0; mi < 2; mi++) {
                    float* c = acc[mi][2 * j + nn];
                    mma_bf16(c, A1[mi].x, A1[mi].y, A1[mi].z, A1[mi].w, B1.x, B1.y);
                    mma_bf16(c, A1[mi].x, A1[mi].y, A1[mi].z, A1[mi].w, B2.x, B2.y);
                    mma_bf16(c, A2[mi].x, A2[mi].y, A2[mi].z, A2[mi].w, B1.x, B1.y);
                }
            }
        }
    }

#pragma unroll
    for (int ni = 0; ni < 4; ni++) {
        float2 bb = *(const float2*)(bias + n0 + nw * 32 + ni * 8 + tig * 2);
#pragma unroll
        for (int mi = 0; mi < 2; mi++) {
            acc[mi][ni][0] += bb.x; acc[mi][ni][1] += bb.y;
            acc[mi][ni][2] += bb.x; acc[mi][ni][3] += bb.y;
        }
    }

#pragma unroll
    for (int mi = 0; mi < 2; mi++) {
        float s0 = 0.f, s1 = 0.f;
#pragma unroll
        for (int ni = 0; ni < 4; ni++) {
            s0 = fmaf(acc[mi][ni][0], acc[mi][ni][0], s0);
            s0 = fmaf(acc[mi][ni][1], acc[mi][ni][1], s0);
            s1 = fmaf(acc[mi][ni][2], acc[mi][ni][2], s1);
            s1 = fmaf(acc[mi][ni][3], acc[mi][ni][3], s1);
        }
        s0 += __shfl_xor_sync(0xFFFFFFFFu, s0, 1);
        s0 += __shfl_xor_sync(0xFFFFFFFFu, s0, 2);
        s1 += __shfl_xor_sync(0xFFFFFFFFu, s1, 1);
        s1 += __shfl_xor_sync(0xFFFFFFFFu, s1, 2);
        if (tig == 0) {
            ssq[qw * 32 + mi * 16 + g][nw] = s0;
            ssq[qw * 32 + mi * 16 + g + 8][nw] = s1;
        }
    }
    __syncthreads();

#pragma unroll
    for (int mi = 0; mi < 2; mi++) {
        const int rg = qw * 32 + mi * 16 + g;
        const float sc0 = scale / fmaxf(sqrtf(ssq[rg][0] + ssq[rg][1]), 1e-12f);
        const float sc1 = scale / fmaxf(sqrtf(ssq[rg + 8][0] + ssq[rg + 8][1]), 1e-12f);
        const int q16 = qt * 8 + qw * 2 + mi;
#pragma unroll
        for (int jj = 0; jj < 2; jj++) {
            const int k16 = nw * 2 + jj;
            float w0 = acc[mi][2 * jj][0] * sc0, w1 = acc[mi][2 * jj][1] * sc0;
            float w2 = acc[mi][2 * jj][2] * sc1, w3 = acc[mi][2 * jj][3] * sc1;
            float w4 = acc[mi][2 * jj + 1][0] * sc0, w5 = acc[mi][2 * jj + 1][1] * sc0;
            float w6 = acc[mi][2 * jj + 1][2] * sc1, w7 = acc[mi][2 * jj + 1][3] * sc1;
            if (isQ) {
                uint4 u1, u2;
                split2pack(w0, w1, u1.x, u2.x);
                split2pack(w2, w3, u1.y, u2.y);
                split2pack(w4, w5, u1.z, u2.z);
                split2pack(w6, w7, u1.w, u2.w);
                const size_t idx = ((bh * 64 + q16) * 4 + k16) * 32 + lane;
                g_wqA1[idx] = u1;
                g_wqA2[idx] = u2;
            } else {
                uint2 ua1, ua2, ub1, ub2;
                split2pack(w0, w1, ua1.x, ua2.x);
                split2pack(w4, w5, ua1.y, ua2.y);
                split2pack(w2, w3, ub1.x, ub2.x);
                split2pack(w6, w7, ub1.y, ub2.y);
                const size_t ia = ((bh * 128 + q16 * 2) * 4 + k16) * 32 + lane;
                const size_t ib2 = ((bh * 128 + q16 * 2 + 1) * 4 + k16) * 32 + lane;
                g_wkB1[ia] = ua1; g_wkB2[ia] = ua2;
                g_wkB1[ib2] = ub1; g_wkB2[ib2] = ub2;
            }
        }
    }
}

// ---------------------------------------------------------------------------
// Kernel 2: V -> B-fragment layout (unchanged).
// ---------------------------------------------------------------------------
__global__ __launch_bounds__(256) void vsplit_kernel(const float* __restrict__ value) {
    __shared__ float t[32][33];
    const int tid = threadIdx.x;
    const int f0 = blockIdx.x * 32, s0 = blockIdx.y * 32, b = blockIdx.z;

    for (int u = tid; u < 1024; u += 256) {
        int s = u >> 5, f = u & 31;
        t[s][f] = value[(size_t)(s0 + s) * (BB * FF) + b * FF + f0 + f];
    }
    __syncthreads();

    const int blk = tid >> 5, lane = tid & 31;
    const int sbk = blk >> 2, fb = blk & 3;
    const int g = lane >> 2, tig = lane & 3;
    const int s_l = sbk * 16 + tig * 2;
    const int f_l = fb * 8 + g;
    __half2 bh0 = __floats2half2_rn(t[s_l][f_l], t[s_l + 1][f_l]);
    __half2 bh1 = __floats2half2_rn(t[s_l + 8][f_l], t[s_l + 9][f_l]);
    uint2 u;
    u.x = *(uint32_t*)&bh0; u.y = *(uint32_t*)&bh1;
    const int f8 = (f0 >> 3) + fb;
    const int s16 = (s0 >> 4) + sbk;
    ((uint2*)g_vt)[(((size_t)b * 64 + f8) * 64 + s16) * 32 + lane] = u;
}

// ---------------------------------------------------------------------------
// Kernel 3 (FUSED, v4): CTA = 64q x 512f, 512 thr (16 warps), 1 CTA/SM.
// Halves V L2 traffic vs 32q. 2 syncthreads per chunk, double-buffered.
// ---------------------------------------------------------------------------
#define FWQ   0        // 16384: wq frag blobs [q16l 4][kc 4][p 2] x 512B
#define FPB   16384    // 2 x 16384: P frag blobs [q16l 4][s16l 8] x 512B
#define FM    49152    // 2 x 64 x 4: running max, double-buffered
#define FL    49664    // 256: running sum
#define FSMAX 49920    // 2 x 64*9*4: chunk-max partials, double-buffered
#define FPS   54528    // 2 x 64*9*4: p-sum partials, double-buffered
#define FUSED_SMEM 59136

__global__ __launch_bounds__(512, 1) void attn_kernel(float* __restrict__ out) {
    const int tid = threadIdx.x;
    const int w = tid >> 5, lane = tid & 31;
    const int g = lane >> 2, tig = lane & 3;
    const int qw = w >> 3, xw = w & 7;
    const int qt = blockIdx.x;           // 0..15 (64 q each)
    const int h = blockIdx.y, b = blockIdx.z;
    const size_t bh = (size_t)b * HH + h;

    float* sm_m   = (float*)(smx + FM);     // [2][64]
    float* sm_l   = (float*)(smx + FL);     // [64]
    float* sm_max = (float*)(smx + FSMAX);  // [2][64][9]
    float* sm_ps  = (float*)(smx + FPS);    // [2][64][9]

    // prologue: stage wq A-frags (4 q16 x 4 kc x 2 parts)
    for (int u = tid; u < 1024; u += 512) {
        const int q16l = u >> 8, kc = (u >> 6) & 3, p = (u >> 5) & 1, ln = u & 31;
        const uint4* src = (p ? g_wqA2 : g_wqA1) +
            ((bh * 64 + qt * 4 + q16l) * 4 + kc) * 32 + ln;
        *(uint4*)(smx + FWQ + u * 16) = *src;
    }
    if (tid < 128) sm_m[tid] = -1e30f;      // both parities
    if (tid < 64) sm_l[tid] = 0.f;
    for (int u = tid; u < 2 * 64 * 9; u += 512) sm_ps[u] = 0.f;
    __syncthreads();

    float oacc[2][8][4] = {};
    const int r0 = qw * 32 + g;

    for (int sc = 0; sc < 8; sc++) {
        const int pw = sc & 1, pr = pw ^ 1;

        // ---- S phase: warp (qw,xw) computes S[32q x 16s] at s16 = sc*8+xw ----
        float sacc[2][2][4] = {};
#pragma unroll
        for (int kc = 0; kc < 4; kc++) {
            uint4 a[2][2];
#pragma unroll
            for (int mi = 0; mi < 2; mi++)
#pragma unroll
                for (int p = 0; p < 2; p++)
                    a[mi][p] = *(const uint4*)(smx + FWQ +
                        (((qw * 2 + mi) * 4 + kc) * 2 + p) * 512 + lane * 16);
#pragma unroll
            for (int nj = 0; nj < 2; nj++) {
                const int n8 = (sc * 8 + xw) * 2 + nj;
                const size_t ib = ((bh * 128 + n8) * 4 + kc) * 32 + lane;
                uint2 B1 = g_wkB1[ib];
                uint2 B2 = g_wkB2[ib];
#pragma unroll
                for (int mi = 0; mi < 2; mi++) {
                    mma_bf16(sacc[mi][nj], a[mi][0].x, a[mi][0].y, a[mi][0].z, a[mi][0].w, B1.x, B1.y);
                    mma_bf16(sacc[mi][nj], a[mi][0].x, a[mi][0].y, a[mi][0].z, a[mi][0].w, B2.x, B2.y);
                    mma_bf16(sacc[mi][nj], a[mi][1].x, a[mi][1].y, a[mi][1].z, a[mi][1].w, B1.x, B1.y);
                }
            }
        }

        // ---- chunk-max partials (buffer pw) ----
#pragma unroll
        for (int mi = 0; mi < 2; mi++) {
            float rm0 = fmaxf(fmaxf(sacc[mi][0][0], sacc[mi][0][1]),
                              fmaxf(sacc[mi][1][0], sacc[mi][1][1]));
            float rm1 = fmaxf(fmaxf(sacc[mi][0][2], sacc[mi][0][3]),
                              fmaxf(sacc[mi][1][2], sacc[mi][1][3]));
            rm0 = fmaxf(rm0, __shfl_xor_sync(0xFFFFFFFFu, rm0, 1));
            rm0 = fmaxf(rm0, __shfl_xor_sync(0xFFFFFFFFu, rm0, 2));
            rm1 = fmaxf(rm1, __shfl_xor_sync(0xFFFFFFFFu, rm1, 1));
            rm1 = fmaxf(rm1, __shfl_xor_sync(0xFFFFFFFFu, rm1, 2));
            if (tig == 0) {
                sm_max[pw * 576 + (r0 + mi * 16) * 9 + xw] = rm0;
                sm_max[pw * 576 + (r0 + mi * 16 + 8) * 9 + xw] = rm1;
            }
        }
        __syncthreads();   // sync A

        // ---- local Mn / rescale; owner (tid<64) updates running state ----
        float mn[2][2], scl[2][2];
#pragma unroll
        for (int mi = 0; mi < 2; mi++)
#pragma unroll
            for (int half = 0; half < 2; half++) {
                const int r = r0 + mi * 16 + half * 8;
                const float* mx = sm_max + pw * 576 + r * 9;
                float cm = fmaxf(fmaxf(fmaxf(mx[0], mx[1]), fmaxf(mx[2], mx[3])),
                                 fmaxf(fmaxf(mx[4], mx[5]), fmaxf(mx[6], mx[7])));
                float Mo = sm_m[pr * 64 + r];
                float Mn = fmaxf(Mo, cm);
                mn[mi][half] = Mn;
                scl[mi][half] = __expf(Mo - Mn);
            }
        if (tid < 64) {
            const float* px = sm_ps + pr * 576 + tid * 9;
            float ps = px[0] + px[1] + px[2] + px[3] + px[4] + px[5] + px[6] + px[7];
            const float* mx = sm_max + pw * 576 + tid * 9;
            float cm = fmaxf(fmaxf(fmaxf(mx[0], mx[1]), fmaxf(mx[2], mx[3])),
                             fmaxf(fmaxf(mx[4], mx[5]), fmaxf(mx[6], mx[7])));
            float Mo = sm_m[pr * 64 + tid];
            float Mn = fmaxf(Mo, cm);
            sm_m[pw * 64 + tid] = Mn;
            sm_l[tid] = (sm_l[tid] + ps) * __expf(Mo - Mn);
        }

        // ---- P = exp(s - Mn) -> fp16 A-frags (buffer pw); rescale oacc ----
#pragma unroll
        for (int mi = 0; mi < 2; mi++) {
            float e[2][4];
#pragma unroll
            for (int nj = 0; nj < 2; nj++) {
                e[nj][0] = __expf(sacc[mi][nj][0] - mn[mi][0]);
                e[nj][1] = __expf(sacc[mi][nj][1] - mn[mi][0]);
                e[nj][2] = __expf(sacc[mi][nj][2] - mn[mi][1]);
                e[nj][3] = __expf(sacc[mi][nj][3] - mn[mi][1]);
            }
            float p0 = e[0][0] + e[0][1] + e[1][0] + e[1][1];
            float p1 = e[0][2] + e[0][3] + e[1][2] + e[1][3];
            p0 += __shfl_xor_sync(0xFFFFFFFFu, p0, 1);
            p0 += __shfl_xor_sync(0xFFFFFFFFu, p0, 2);
            p1 += __shfl_xor_sync(0xFFFFFFFFu, p1, 1);
            p1 += __shfl_xor_sync(0xFFFFFFFFu, p1, 2);
            if (tig == 0) {
                sm_ps[pw * 576 + (r0 + mi * 16) * 9 + xw] = p0;
                sm_ps[pw * 576 + (r0 + mi * 16 + 8) * 9 + xw] = p1;
            }
            __half2 h0 = __floats2half2_rn(e[0][0], e[0][1]);
            __half2 h1 = __floats2half2_rn(e[0][2], e[0][3]);
            __half2 h2 = __floats2half2_rn(e[1][0], e[1][1]);
            __half2 h3 = __floats2half2_rn(e[1][2], e[1][3]);
            uint4 u;
            u.x = *(uint32_t*)&h0; u.y = *(uint32_t*)&h1;
            u.z = *(uint32_t*)&h2; u.w = *(uint32_t*)&h3;
            *(uint4*)(smx + FPB + pw * 16384 + ((qw * 2 + mi) * 8 + xw) * 512 + lane * 16) = u;

#pragma unroll
            for (int ni = 0; ni < 8; ni++) {
                oacc[mi][ni][0] *= scl[mi][0]; oacc[mi][ni][1] *= scl[mi][0];
                oacc[mi][ni][2] *= scl[mi][1]; oacc[mi][ni][3] *= scl[mi][1];
            }
        }
        __syncthreads();   // sync B

        // ---- PV phase: warp (qw,xw) = 32q x 64f; V frag reused for 2 q16 ----
#pragma unroll
        for (int kk = 0; kk < 8; kk++) {
            uint4 au0 = *(const uint4*)(smx + FPB + pw * 16384 +
                                        ((qw * 2 + 0) * 8 + kk) * 512 + lane * 16);
            uint4 au1 = *(const uint4*)(smx + FPB + pw * 16384 +
                                        ((qw * 2 + 1) * 8 + kk) * 512 + lane * 16);
#pragma unroll
            for (int ni = 0; ni < 8; ni++) {
                uint2 v = ((const uint2*)g_vt)[
                    (((size_t)b * 64 + xw * 8 + ni) * 64 + sc * 8 + kk) * 32 + lane];
                mma_f16(oacc[0][ni], au0.x, au0.y, au0.z, au0.w, v.x, v.y);
                mma_f16(oacc[1][ni], au1.x, au1.y, au1.z, au1.w, v.x, v.y);
            }
        }
    }

    // ---- epilogue ----
    float iv[2][2];
#pragma unroll
    for (int mi = 0; mi < 2; mi++)
#pragma unroll
        for (int half = 0; half < 2; half++) {
            const int r = r0 + mi * 16 + half * 8;
            const float* px = sm_ps + 576 + r * 9;   // parity of sc=7 is 1
            float ps = px[0] + px[1] + px[2] + px[3] + px[4] + px[5] + px[6] + px[7];
            iv[mi][half] = 1.0f / (sm_l[r] + ps);
        }

#pragma unroll
    for (int mi = 0; mi < 2; mi++) {
        const int q0 = qt * 64 + qw * 32 + mi * 16 + g;
#pragma unroll
        for (int ni = 0; ni < 8; ni++) {
            const int f = (xw * 8 + ni) * 8 + tig * 2;
            float* op0 = out + ((size_t)q0 * BB + b) * (HH * FF) + h * FF + f;
            float* op1 = out + ((size_t)(q0 + 8) * BB + b) * (HH * FF) + h * FF + f;
            *(float2*)op0 = make_float2(oacc[mi][ni][0] * iv[mi][0], oacc[mi][ni][1] * iv[mi][0]);
            *(float2*)op1 = make_float2(oacc[mi][ni][2] * iv[mi][1], oacc[mi][ni][3] * iv[mi][1]);
        }
    }
}

// ---------------------------------------------------------------------------
extern "C" void kernel_launch(void* const* d_in, const int* in_sizes, int n_in,
                              void* d_out, int out_size) {
    const float* query = (const float*)d_in[0];
    const float* key   = (const float*)d_in[1];
    const float* value = (const float*)d_in[2];
    const float* Wk    = (const float*)d_in[3];
    const float* bk    = (const float*)d_in[4];
    float* out = (float*)d_out;

    wsplit_kernel<<<64, 256>>>(Wk);
    dim3 xg(64, 16, 2);
    xsplit_kernel<<<xg, 256>>>(query, key);

    dim3 pg(8 * 16, HH, 2);
    projmma_kernel<<<pg, 256>>>(bk);

    dim3 vg(FF / 32, LQ / 32, BB);
    vsplit_kernel<<<vg, 256>>>(value);

    cudaFuncSetAttribute(attn_kernel, cudaFuncAttributeMaxDynamicSharedMemorySize, FUSED_SMEM);
    dim3 ag(16, HH, BB);   // 2048 CTAs
    attn_kernel<<<ag, 512, FUSED_SMEM>>>(out);
}